// round 6
// baseline (speedup 1.0000x reference)
#include <cuda_runtime.h>
#include <cuda_bf16.h>

#define BMAX 16384

// Scratch (static device globals — no allocation).
// Layout: [b][p][o20], 16384*8*20 floats each = 10.5 MB each (L2-resident together).
__device__ float g_U[BMAX * 8 * 20];
__device__ float g_V[BMAX * 8 * 20];

// PHASE_LANES = [[1,3],[5,7],[0,2],[4,6],[0,1],[2,3],[4,5],[6,7]]
__device__ const int d_PLa[8] = {1, 5, 0, 4, 0, 2, 4, 6};
__device__ const int d_PLb[8] = {3, 7, 2, 6, 1, 3, 5, 7};

__device__ __forceinline__ float sigmoidf(float x) {
    return 1.0f / (1.0f + __expf(-x));
}

// ---------------------------------------------------------------------------
// Kernel 1: per (b, p) compute pressure[p][0:16] and the decomposed first
// feature layer: U[b,p,o] = w_feat[o,0:16]·press, V[b,p,o] = w_feat[o,16:32]·press
// ---------------------------------------------------------------------------
__global__ void frap_k1(const float* __restrict__ fi,
                        const float* __restrict__ emb_phase,
                        const float* __restrict__ w_veh,
                        const float* __restrict__ b_veh,
                        const float* __restrict__ w_line,
                        const float* __restrict__ b_line,
                        const float* __restrict__ w_feat,
                        int B)
{
    __shared__ __align__(16) float s_wline[128];   // (16,8)
    __shared__ __align__(16) float s_wfeat[640];   // (20,32)
    __shared__ float s_bline[16];
    __shared__ float s_emb[8];                     // (2,4)
    __shared__ float s_wv[4], s_bv[4];

    int tx = threadIdx.x;
    for (int idx = tx; idx < 128; idx += blockDim.x) s_wline[idx] = w_line[idx];
    for (int idx = tx; idx < 640; idx += blockDim.x) s_wfeat[idx] = w_feat[idx];
    if (tx < 16) s_bline[tx] = b_line[tx];
    if (tx < 8)  s_emb[tx]   = emb_phase[tx];
    if (tx < 4)  { s_wv[tx] = w_veh[tx]; s_bv[tx] = b_veh[tx]; }
    __syncthreads();

    int tid = blockIdx.x * blockDim.x + tx;
    if (tid >= B * 8) return;
    int b = tid >> 3;
    int p = tid & 7;

    int la = d_PLa[p];
    int lb = d_PLb[p];

    const float* f = fi + (size_t)b * 16;
    float bit_a = f[la],     bit_b = f[lb];
    float veh_a = f[8 + la], veh_b = f[8 + lb];
    int ia = (int)bit_a, ib = (int)bit_b;

    // lines = [fv(4), fp(4)]
    float lineA[8], lineB[8];
#pragma unroll
    for (int d = 0; d < 4; d++) {
        lineA[d]     = sigmoidf(veh_a * s_wv[d] + s_bv[d]);
        lineB[d]     = sigmoidf(veh_b * s_wv[d] + s_bv[d]);
        lineA[4 + d] = sigmoidf(s_emb[ia * 4 + d]);
        lineB[4 + d] = sigmoidf(s_emb[ib * 4 + d]);
    }

    // pressure[o] = relu(wl[o]·lineA + bl[o]) + relu(wl[o]·lineB + bl[o])
    float press[16];
#pragma unroll
    for (int o = 0; o < 16; o++) {
        const float* w = &s_wline[o * 8];
        float xa = s_bline[o];
        float xb = s_bline[o];
#pragma unroll
        for (int d = 0; d < 8; d++) {
            xa += w[d] * lineA[d];
            xb += w[d] * lineB[d];
        }
        press[o] = fmaxf(xa, 0.0f) + fmaxf(xb, 0.0f);
    }

    // U/V decomposition of the 20x32 feature layer
    size_t base = (size_t)tid * 20;   // tid == b*8+p -> layout [b][p][o]
#pragma unroll
    for (int o = 0; o < 20; o++) {
        const float* w = &s_wfeat[o * 32];
        float u = 0.0f, v = 0.0f;
#pragma unroll
        for (int c = 0; c < 16; c++) {
            u += w[c]      * press[c];
            v += w[16 + c] * press[c];
        }
        g_U[base + o] = u;
        g_V[base + o] = v;
    }
}

// ---------------------------------------------------------------------------
// Kernel 2: one thread per output element (b', i). For j=0..6 it gathers
// U[b,pi], V[b,pj] with (pair*B + b) = 56*b' + 7*i + j, applies the
// relu/scale, the 20x20 comb layer, the final 20->1 layer, and accumulates.
// ---------------------------------------------------------------------------
__global__ void frap_k2(const float* __restrict__ emb_const,
                        const float* __restrict__ b_feat,
                        const float* __restrict__ w_const,
                        const float* __restrict__ b_const,
                        const float* __restrict__ w_comb,
                        const float* __restrict__ b_comb,
                        const float* __restrict__ w_final,
                        const float* __restrict__ b_final,
                        const int*   __restrict__ cmask,
                        float* __restrict__ out,
                        int B)
{
    __shared__ __align__(16) float s_yc[56 * 20];   // relu(w_const·emb_const[mask]+b_const)
    __shared__ __align__(16) float s_wcomb[400];    // (20,20)
    __shared__ float s_bcomb[20];
    __shared__ float s_wfin[20];
    __shared__ float s_bfeat[20];
    __shared__ float s_bfin;

    int tx = threadIdx.x;
    for (int idx = tx; idx < 400; idx += blockDim.x) s_wcomb[idx] = w_comb[idx];
    if (tx < 20) {
        s_bcomb[tx] = b_comb[tx];
        s_wfin[tx]  = w_final[tx];
        s_bfeat[tx] = b_feat[tx];
    }
    if (tx == 0) s_bfin = b_final[0];
    for (int idx = tx; idx < 56 * 20; idx += blockDim.x) {
        int k = idx / 20;
        int o = idx - k * 20;
        const float* e = emb_const + cmask[k] * 4;
        const float* w = w_const + o * 4;
        float a = b_const[o] + w[0] * e[0] + w[1] * e[1] + w[2] * e[2] + w[3] * e[3];
        s_yc[idx] = fmaxf(a, 0.0f);
    }
    __syncthreads();

    int tid = blockIdx.x * blockDim.x + tx;
    if (tid >= B * 8) return;
    int bp = tid >> 3;     // b'
    int i  = tid & 7;

    unsigned t    = (unsigned)(56 * bp + 7 * i);
    unsigned pair = t / (unsigned)B;               // one division per thread
    int      b    = (int)(t - pair * (unsigned)B);

    const float* ycr = &s_yc[(i * 7) * 20];
    float acc = 0.0f;

    for (int j = 0; j < 7; j++) {
        int pp = (int)pair;
        int pi = pp / 7;                           // off-diagonal pair decode
        int r  = pp - pi * 7;
        int pj = r + (r >= pi ? 1 : 0);

        const float4* up = (const float4*)(g_U + ((size_t)b * 8 + pi) * 20);
        const float4* vp = (const float4*)(g_V + ((size_t)b * 8 + pj) * 20);

        // h[o] = relu(U+V+b_feat) * yc   (first layer + const-branch multiply)
        float h[20];
#pragma unroll
        for (int q = 0; q < 5; q++) {
            float4 u = up[q];
            float4 v = vp[q];
            h[q * 4 + 0] = fmaxf(u.x + v.x + s_bfeat[q * 4 + 0], 0.0f) * ycr[q * 4 + 0];
            h[q * 4 + 1] = fmaxf(u.y + v.y + s_bfeat[q * 4 + 1], 0.0f) * ycr[q * 4 + 1];
            h[q * 4 + 2] = fmaxf(u.z + v.z + s_bfeat[q * 4 + 2], 0.0f) * ycr[q * 4 + 2];
            h[q * 4 + 3] = fmaxf(u.w + v.w + s_bfeat[q * 4 + 3], 0.0f) * ycr[q * 4 + 3];
        }

        // comb (20x20) + final (20->1), fused
        float s = s_bfin;
#pragma unroll
        for (int o2 = 0; o2 < 20; o2++) {
            const float4* w = (const float4*)&s_wcomb[o2 * 20];
            float a = s_bcomb[o2];
#pragma unroll
            for (int q = 0; q < 5; q++) {
                float4 ww = w[q];
                a += ww.x * h[q * 4 + 0] + ww.y * h[q * 4 + 1]
                   + ww.z * h[q * 4 + 2] + ww.w * h[q * 4 + 3];
            }
            s += fmaxf(a, 0.0f) * s_wfin[o2];
        }
        acc += fmaxf(s, 0.0f);

        ycr += 20;
        // t increments by 1 per j: advance (b, pair) without re-dividing
        if (++b == B) { b = 0; ++pair; }
    }

    out[tid] = acc;   // out[b'*8 + i]
}

// ---------------------------------------------------------------------------
extern "C" void kernel_launch(void* const* d_in, const int* in_sizes, int n_in,
                              void* d_out, int out_size)
{
    const float* fi        = (const float*)d_in[0];
    const float* emb_phase = (const float*)d_in[1];
    const float* w_veh     = (const float*)d_in[2];
    const float* b_veh     = (const float*)d_in[3];
    const float* w_line    = (const float*)d_in[4];
    const float* b_line    = (const float*)d_in[5];
    const float* emb_const = (const float*)d_in[6];
    const float* w_feat    = (const float*)d_in[7];
    const float* b_feat    = (const float*)d_in[8];
    const float* w_const   = (const float*)d_in[9];
    const float* b_const   = (const float*)d_in[10];
    const float* w_comb    = (const float*)d_in[11];
    const float* b_comb    = (const float*)d_in[12];
    const float* w_final   = (const float*)d_in[13];
    const float* b_final   = (const float*)d_in[14];
    const int*   cmask     = (const int*)d_in[15];

    int B = in_sizes[0] / 16;
    if (B > BMAX) B = BMAX;   // scratch bound (reference uses B=16384)

    int n = B * 8;
    int blocks = (n + 255) / 256;

    frap_k1<<<blocks, 256>>>(fi, emb_phase, w_veh, b_veh, w_line, b_line, w_feat, B);
    frap_k2<<<blocks, 256>>>(emb_const, b_feat, w_const, b_const, w_comb, b_comb,
                             w_final, b_final, cmask, (float*)d_out, B);
}

// round 7
// speedup vs baseline: 1.9604x; 1.9604x over previous
#include <cuda_runtime.h>
#include <cuda_bf16.h>

#define BMAX 16384

// Scratch (static device globals — no allocation).
// g_U has b_feat folded in. Layout [b][p][o20], 10.5 MB each -> L2-resident.
__device__ float g_U[BMAX * 8 * 20];
__device__ float g_V[BMAX * 8 * 20];

// PHASE_LANES = [[1,3],[5,7],[0,2],[4,6],[0,1],[2,3],[4,5],[6,7]]
__device__ const int d_PLa[8] = {1, 5, 0, 4, 0, 2, 4, 6};
__device__ const int d_PLb[8] = {3, 7, 2, 6, 1, 3, 5, 7};

__device__ __forceinline__ float sigmoidf(float x) {
    return 1.0f / (1.0f + __expf(-x));
}

__device__ __forceinline__ unsigned long long pk2(float lo, float hi) {
    unsigned long long r;
    asm("mov.b64 %0, {%1, %2};" : "=l"(r) : "f"(lo), "f"(hi));
    return r;
}
__device__ __forceinline__ void upk2(float& lo, float& hi, unsigned long long v) {
    asm("mov.b64 {%0, %1}, %2;" : "=f"(lo), "=f"(hi) : "l"(v));
}
// d = a*b + c on packed f32x2 (bit-identical to two scalar fma.rn.f32)
__device__ __forceinline__ unsigned long long f2fma(unsigned long long a,
                                                    unsigned long long b,
                                                    unsigned long long c) {
    unsigned long long d;
    asm("fma.rn.f32x2 %0, %1, %2, %3;" : "=l"(d) : "l"(a), "l"(b), "l"(c));
    return d;
}

// ---------------------------------------------------------------------------
// Kernel 1: per (b, p): pressure[0:16], then
//   g_U[b,p,o] = w_feat[o,0:16]·press + b_feat[o]
//   g_V[b,p,o] = w_feat[o,16:32]·press
// ---------------------------------------------------------------------------
__global__ void __launch_bounds__(256, 3)
frap_k1(const float* __restrict__ fi,
        const float* __restrict__ emb_phase,
        const float* __restrict__ w_veh,
        const float* __restrict__ b_veh,
        const float* __restrict__ w_line,
        const float* __restrict__ b_line,
        const float* __restrict__ w_feat,
        const float* __restrict__ b_feat,
        int B)
{
    __shared__ __align__(16) float s_wline[128];   // (16,8)
    __shared__ __align__(16) float s_wfeat[640];   // (20,32)
    __shared__ float s_bline[16];
    __shared__ float s_bfeat[20];
    __shared__ float s_emb[8];                     // (2,4)
    __shared__ float s_wv[4], s_bv[4];

    int tx = threadIdx.x;
    for (int idx = tx; idx < 128; idx += blockDim.x) s_wline[idx] = w_line[idx];
    for (int idx = tx; idx < 640; idx += blockDim.x) s_wfeat[idx] = w_feat[idx];
    if (tx < 16) s_bline[tx] = b_line[tx];
    if (tx < 20) s_bfeat[tx] = b_feat[tx];
    if (tx < 8)  s_emb[tx]   = emb_phase[tx];
    if (tx < 4)  { s_wv[tx] = w_veh[tx]; s_bv[tx] = b_veh[tx]; }
    __syncthreads();

    int tid = blockIdx.x * blockDim.x + tx;
    if (tid >= B * 8) return;
    int b = tid >> 3;
    int p = tid & 7;

    int la = d_PLa[p];
    int lb = d_PLb[p];

    const float* f = fi + (size_t)b * 16;
    float bit_a = f[la],     bit_b = f[lb];
    float veh_a = f[8 + la], veh_b = f[8 + lb];
    int ia = (int)bit_a, ib = (int)bit_b;

    float lineA[8], lineB[8];
#pragma unroll
    for (int d = 0; d < 4; d++) {
        lineA[d]     = sigmoidf(veh_a * s_wv[d] + s_bv[d]);
        lineB[d]     = sigmoidf(veh_b * s_wv[d] + s_bv[d]);
        lineA[4 + d] = sigmoidf(s_emb[ia * 4 + d]);
        lineB[4 + d] = sigmoidf(s_emb[ib * 4 + d]);
    }

    float press[16];
#pragma unroll
    for (int o = 0; o < 16; o++) {
        const float* w = &s_wline[o * 8];
        float xa = s_bline[o];
        float xb = s_bline[o];
#pragma unroll
        for (int d = 0; d < 8; d++) {
            xa += w[d] * lineA[d];
            xb += w[d] * lineB[d];
        }
        press[o] = fmaxf(xa, 0.0f) + fmaxf(xb, 0.0f);
    }

    size_t base = (size_t)tid * 20;
#pragma unroll 4
    for (int o = 0; o < 20; o++) {
        const float* w = &s_wfeat[o * 32];
        float u = 0.0f, v = 0.0f;
#pragma unroll
        for (int c = 0; c < 16; c++) {
            u += w[c]      * press[c];
            v += w[16 + c] * press[c];
        }
        g_U[base + o] = u + s_bfeat[o];
        g_V[base + o] = v;
    }
}

// ---------------------------------------------------------------------------
// Kernel 2: thread per (b', i). Gathers 7 positions' U/V, computes
// h = relu(U+V)*yc, then the fused comb(20x20)+final(20->1) layer on
// 4-position batches with f32x2-packed FMA (position pairs), sums relu(s).
// ---------------------------------------------------------------------------
__global__ void __launch_bounds__(128, 3)
frap_k2(const float* __restrict__ emb_const,
        const float* __restrict__ w_const,
        const float* __restrict__ b_const,
        const float* __restrict__ w_comb,
        const float* __restrict__ b_comb,
        const float* __restrict__ w_final,
        const float* __restrict__ b_final,
        const int*   __restrict__ cmask,
        float* __restrict__ out,
        int B)
{
    __shared__ __align__(16) float              s_yc[56 * 20];  // const branch, per (i,j)
    __shared__ __align__(16) unsigned long long s_wd[400];      // dup-packed w_comb[o2][o]
    __shared__ unsigned long long s_bcd[20];                    // dup-packed b_comb
    __shared__ float s_wfin[20];
    __shared__ float s_bfin;

    int tx = threadIdx.x;
    for (int idx = tx; idx < 400; idx += blockDim.x) {
        float w = w_comb[idx];
        s_wd[idx] = pk2(w, w);
    }
    if (tx < 20) {
        float bc = b_comb[tx];
        s_bcd[tx]  = pk2(bc, bc);
        s_wfin[tx] = w_final[tx];
    }
    if (tx == 0) s_bfin = b_final[0];
    for (int idx = tx; idx < 56 * 20; idx += blockDim.x) {
        int k = idx / 20;
        int o = idx - k * 20;
        const float* e = emb_const + cmask[k] * 4;
        const float* w = w_const + o * 4;
        float a = b_const[o] + w[0] * e[0] + w[1] * e[1] + w[2] * e[2] + w[3] * e[3];
        s_yc[idx] = fmaxf(a, 0.0f);
    }
    __syncthreads();

    int tid = blockIdx.x * blockDim.x + tx;
    if (tid >= B * 8) return;
    int bp = tid >> 3;     // b'
    int i  = tid & 7;

    unsigned t    = (unsigned)(56 * bp + 7 * i);
    unsigned pair = t / (unsigned)B;
    int      b    = (int)(t - pair * (unsigned)B);

    const float* yc0 = &s_yc[(i * 7) * 20];
    float acc = 0.0f;

    // two 4-position groups: {0,1,2,3}, {4,5,6,6-dup}
#pragma unroll
    for (int g = 0; g < 2; g++) {
        unsigned long long Hp0[20];   // packed (pos0, pos1)
        unsigned long long Hp1[20];   // packed (pos2, pos3)

        // ---- build 4 h-vectors (pairwise packed) ----
#pragma unroll
        for (int half = 0; half < 2; half++) {
            float ha[20];
#pragma unroll
            for (int sub = 0; sub < 2; sub++) {
                int j = g * 4 + half * 2 + sub;
                bool dummy = (j > 6);
                int jj = dummy ? 6 : j;

                int pp = (int)pair;
                int pi = pp / 7;
                int r  = pp - pi * 7;
                int pj = r + (r >= pi ? 1 : 0);

                const float4* up = (const float4*)(g_U + ((size_t)b * 8 + pi) * 20);
                const float4* vp = (const float4*)(g_V + ((size_t)b * 8 + pj) * 20);
                const float* ycr = yc0 + jj * 20;

                if (sub == 0) {
#pragma unroll
                    for (int q = 0; q < 5; q++) {
                        float4 u = up[q];
                        float4 v = vp[q];
                        ha[q * 4 + 0] = fmaxf(u.x + v.x, 0.0f) * ycr[q * 4 + 0];
                        ha[q * 4 + 1] = fmaxf(u.y + v.y, 0.0f) * ycr[q * 4 + 1];
                        ha[q * 4 + 2] = fmaxf(u.z + v.z, 0.0f) * ycr[q * 4 + 2];
                        ha[q * 4 + 3] = fmaxf(u.w + v.w, 0.0f) * ycr[q * 4 + 3];
                    }
                } else {
                    unsigned long long* Hp = (half == 0) ? Hp0 : Hp1;
#pragma unroll
                    for (int q = 0; q < 5; q++) {
                        float4 u = up[q];
                        float4 v = vp[q];
                        Hp[q * 4 + 0] = pk2(ha[q * 4 + 0], fmaxf(u.x + v.x, 0.0f) * ycr[q * 4 + 0]);
                        Hp[q * 4 + 1] = pk2(ha[q * 4 + 1], fmaxf(u.y + v.y, 0.0f) * ycr[q * 4 + 1]);
                        Hp[q * 4 + 2] = pk2(ha[q * 4 + 2], fmaxf(u.z + v.z, 0.0f) * ycr[q * 4 + 2]);
                        Hp[q * 4 + 3] = pk2(ha[q * 4 + 3], fmaxf(u.w + v.w, 0.0f) * ycr[q * 4 + 3]);
                    }
                }
                // advance position state (skip on dummy)
                if (!dummy) {
                    if (++b == B) { b = 0; ++pair; }
                }
            }
        }

        // ---- comb (20x20) + final (20->1), 4 positions per weight pass ----
        float s0 = s_bfin, s1 = s_bfin, s2 = s_bfin, s3 = s_bfin;
#pragma unroll 4
        for (int o2 = 0; o2 < 20; o2++) {
            const ulonglong2* wrow = (const ulonglong2*)(s_wd + o2 * 20);
            unsigned long long bcd = s_bcd[o2];
            unsigned long long a0 = bcd;
            unsigned long long a1 = bcd;
#pragma unroll
            for (int k = 0; k < 10; k++) {
                ulonglong2 w2 = wrow[k];
                a0 = f2fma(w2.x, Hp0[2 * k],     a0);
                a1 = f2fma(w2.x, Hp1[2 * k],     a1);
                a0 = f2fma(w2.y, Hp0[2 * k + 1], a0);
                a1 = f2fma(w2.y, Hp1[2 * k + 1], a1);
            }
            float lo0, hi0, lo1, hi1;
            upk2(lo0, hi0, a0);
            upk2(lo1, hi1, a1);
            float wf = s_wfin[o2];
            s0 += fmaxf(lo0, 0.0f) * wf;
            s1 += fmaxf(hi0, 0.0f) * wf;
            s2 += fmaxf(lo1, 0.0f) * wf;
            s3 += fmaxf(hi1, 0.0f) * wf;
        }

        acc += fmaxf(s0, 0.0f) + fmaxf(s1, 0.0f) + fmaxf(s2, 0.0f);
        if (g == 0) acc += fmaxf(s3, 0.0f);   // group 1's 4th slot is the dummy
    }

    out[tid] = acc;
}

// ---------------------------------------------------------------------------
extern "C" void kernel_launch(void* const* d_in, const int* in_sizes, int n_in,
                              void* d_out, int out_size)
{
    const float* fi        = (const float*)d_in[0];
    const float* emb_phase = (const float*)d_in[1];
    const float* w_veh     = (const float*)d_in[2];
    const float* b_veh     = (const float*)d_in[3];
    const float* w_line    = (const float*)d_in[4];
    const float* b_line    = (const float*)d_in[5];
    const float* emb_const = (const float*)d_in[6];
    const float* w_feat    = (const float*)d_in[7];
    const float* b_feat    = (const float*)d_in[8];
    const float* w_const   = (const float*)d_in[9];
    const float* b_const   = (const float*)d_in[10];
    const float* w_comb    = (const float*)d_in[11];
    const float* b_comb    = (const float*)d_in[12];
    const float* w_final   = (const float*)d_in[13];
    const float* b_final   = (const float*)d_in[14];
    const int*   cmask     = (const int*)d_in[15];

    int B = in_sizes[0] / 16;
    if (B > BMAX) B = BMAX;

    int n = B * 8;
    int blocks1 = (n + 255) / 256;
    int blocks2 = (n + 127) / 128;

    frap_k1<<<blocks1, 256>>>(fi, emb_phase, w_veh, b_veh, w_line, b_line,
                              w_feat, b_feat, B);
    frap_k2<<<blocks2, 128>>>(emb_const, w_const, b_const, w_comb, b_comb,
                              w_final, b_final, cmask, (float*)d_out, B);
}

// round 8
// speedup vs baseline: 3.1330x; 1.5982x over previous
#include <cuda_runtime.h>
#include <cuda_bf16.h>

#define BMAX 16384

typedef unsigned long long u64;

// Scratch (static device globals — no allocation).
// Pair-interleaved layout: g_U4[p][o2][bh] (p<8, o2<10, bh<B/2), float4 =
//   { U[2bh][p][2o2], U[2bh][p][2o2+1], U[2bh+1][p][2o2], U[2bh+1][p][2o2+1] }
// (b_feat folded into U). Same for V. 10.5 MB each -> L2-resident.
__device__ float4 g_U4[8 * 10 * (BMAX / 2)];
__device__ float4 g_V4[8 * 10 * (BMAX / 2)];
// per-position relu(final) values, summed in groups of 7 by k3
__device__ float g_S[BMAX * 56];

// PHASE_LANES = [[1,3],[5,7],[0,2],[4,6],[0,1],[2,3],[4,5],[6,7]]
__device__ const int d_PLa[8] = {1, 5, 0, 4, 0, 2, 4, 6};
__device__ const int d_PLb[8] = {3, 7, 2, 6, 1, 3, 5, 7};

__device__ __forceinline__ float sigmoidf(float x) {
    return __fdividef(1.0f, 1.0f + __expf(-x));
}
__device__ __forceinline__ u64 pk2(float lo, float hi) {
    u64 r;
    asm("mov.b64 %0, {%1, %2};" : "=l"(r) : "f"(lo), "f"(hi));
    return r;
}
__device__ __forceinline__ void upk2(float& lo, float& hi, u64 v) {
    asm("mov.b64 {%0, %1}, %2;" : "=f"(lo), "=f"(hi) : "l"(v));
}
__device__ __forceinline__ u64 f2fma(u64 a, u64 b, u64 c) {
    u64 d;
    asm("fma.rn.f32x2 %0, %1, %2, %3;" : "=l"(d) : "l"(a), "l"(b), "l"(c));
    return d;
}
__device__ __forceinline__ u64 f2mul(u64 a, u64 b) {
    u64 d;
    asm("mul.rn.f32x2 %0, %1, %2;" : "=l"(d) : "l"(a), "l"(b));
    return d;
}

// ---------------------------------------------------------------------------
// Kernel 1: grid (B/256, 8); p = blockIdx.y (lane-pair phase), b fast across
// lanes. Computes press[16], then packed (U,V) projections, stores
// pair-interleaved coalesced float2s.
// ---------------------------------------------------------------------------
__global__ void __launch_bounds__(256, 2)
frap_k1(const float* __restrict__ fi,
        const float* __restrict__ emb_phase,
        const float* __restrict__ w_veh,
        const float* __restrict__ b_veh,
        const float* __restrict__ w_line,
        const float* __restrict__ b_line,
        const float* __restrict__ w_feat,
        const float* __restrict__ b_feat,
        int B)
{
    __shared__ __align__(16) float s_wline[128];   // (16,8)
    __shared__ __align__(16) u64   s_wpk[320];     // (20,16): (w_feat[o][c], w_feat[o][16+c])
    __shared__ float s_bline[16];
    __shared__ float s_bfeat[20];
    __shared__ float s_emb[8];
    __shared__ float s_wv[4], s_bv[4];

    int tx = threadIdx.x;
    for (int idx = tx; idx < 128; idx += 256) s_wline[idx] = w_line[idx];
    for (int idx = tx; idx < 320; idx += 256) {
        int o = idx >> 4, c = idx & 15;
        s_wpk[idx] = pk2(w_feat[o * 32 + c], w_feat[o * 32 + 16 + c]);
    }
    if (tx < 16) s_bline[tx] = b_line[tx];
    if (tx < 20) s_bfeat[tx] = b_feat[tx];
    if (tx < 8)  s_emb[tx]   = emb_phase[tx];
    if (tx < 4)  { s_wv[tx] = w_veh[tx]; s_bv[tx] = b_veh[tx]; }
    __syncthreads();

    int b = blockIdx.x * 256 + tx;
    if (b >= B) return;
    int p  = blockIdx.y;
    int la = d_PLa[p];
    int lb = d_PLb[p];

    const float* f = fi + (size_t)b * 16;
    float bit_a = f[la],     bit_b = f[lb];
    float veh_a = f[8 + la], veh_b = f[8 + lb];
    int ia = (int)bit_a, ib = (int)bit_b;

    float lineA[8], lineB[8];
#pragma unroll
    for (int d = 0; d < 4; d++) {
        lineA[d]     = sigmoidf(veh_a * s_wv[d] + s_bv[d]);
        lineB[d]     = sigmoidf(veh_b * s_wv[d] + s_bv[d]);
        lineA[4 + d] = sigmoidf(s_emb[ia * 4 + d]);
        lineB[4 + d] = sigmoidf(s_emb[ib * 4 + d]);
    }

    u64 pressd[16];
#pragma unroll
    for (int o = 0; o < 16; o++) {
        const float* w = &s_wline[o * 8];
        float xa = s_bline[o], xb = s_bline[o];
#pragma unroll
        for (int d = 0; d < 8; d++) {
            xa += w[d] * lineA[d];
            xb += w[d] * lineB[d];
        }
        float pr = fmaxf(xa, 0.0f) + fmaxf(xb, 0.0f);
        pressd[o] = pk2(pr, pr);
    }

    int Bh = B >> 1;
    int bh = b >> 1;
    int sub = b & 1;
    float2* stU = (float2*)g_U4;
    float2* stV = (float2*)g_V4;

#pragma unroll
    for (int o2 = 0; o2 < 10; o2++) {
        int oA = 2 * o2, oB = 2 * o2 + 1;
        u64 accA = pk2(s_bfeat[oA], 0.0f);   // (U incl bias, V)
        u64 accB = pk2(s_bfeat[oB], 0.0f);
#pragma unroll
        for (int c = 0; c < 16; c++) {
            accA = f2fma(s_wpk[oA * 16 + c], pressd[c], accA);
            accB = f2fma(s_wpk[oB * 16 + c], pressd[c], accB);
        }
        float uA, vA, uB, vB;
        upk2(uA, vA, accA);
        upk2(uB, vB, accB);
        size_t idx = ((size_t)(p * 10 + o2) * Bh + bh) * 2 + sub;
        stU[idx] = make_float2(uA, uB);
        stV[idx] = make_float2(vA, vB);
    }
}

// ---------------------------------------------------------------------------
// Kernel 2: grid (Bh/256, 56). pair = blockIdx.y (warp-uniform pi/pj),
// thread handles positions t = pair*B + 2*bh, t+1 (coalesced gathers).
// h = relu(U+V)*yc (f32x2-packed over the position pair), then the fused
// comb(20x20)+final layer; writes relu(s) per position to g_S.
// ---------------------------------------------------------------------------
__global__ void __launch_bounds__(256, 2)
frap_k2(const float* __restrict__ emb_const,
        const float* __restrict__ w_const,
        const float* __restrict__ b_const,
        const float* __restrict__ w_comb,
        const float* __restrict__ b_comb,
        const float* __restrict__ w_final,
        const float* __restrict__ b_final,
        const int*   __restrict__ cmask,
        int B)
{
    __shared__ __align__(16) u64 s_ycp[28 * 20];  // (yc[2r][o], yc[2r+1][o])
    __shared__ __align__(16) u64 s_wd[400];       // dup-packed w_comb
    __shared__ u64   s_bcd[20];
    __shared__ float s_wfin[20];
    __shared__ float s_bfin;

    int tx = threadIdx.x;
    for (int idx = tx; idx < 400; idx += 256) {
        float w = w_comb[idx];
        s_wd[idx] = pk2(w, w);
    }
    if (tx < 20) {
        float bc = b_comb[tx];
        s_bcd[tx]  = pk2(bc, bc);
        s_wfin[tx] = w_final[tx];
    }
    if (tx == 0) s_bfin = b_final[0];
    for (int idx = tx; idx < 28 * 20; idx += 256) {
        int r2 = idx / 20;
        int o  = idx - r2 * 20;
        const float* w  = w_const + o * 4;
        const float* e0 = emb_const + cmask[2 * r2] * 4;
        const float* e1 = emb_const + cmask[2 * r2 + 1] * 4;
        float y0 = b_const[o] + w[0]*e0[0] + w[1]*e0[1] + w[2]*e0[2] + w[3]*e0[3];
        float y1 = b_const[o] + w[0]*e1[0] + w[1]*e1[1] + w[2]*e1[2] + w[3]*e1[3];
        s_ycp[idx] = pk2(fmaxf(y0, 0.0f), fmaxf(y1, 0.0f));
    }
    __syncthreads();

    int Bh = B >> 1;
    int bh = blockIdx.x * 256 + tx;
    if (bh >= Bh) return;
    int pair = blockIdx.y;
    int pi = pair / 7;
    int r  = pair - pi * 7;
    int pj = r + (r >= pi ? 1 : 0);

    int t   = pair * B + 2 * bh;     // even
    int rem = t % 56;                // even
    const u64* ycp = s_ycp + (rem >> 1) * 20;

    const float4* Ub = g_U4 + (size_t)pi * 10 * Bh + bh;
    const float4* Vb = g_V4 + (size_t)pj * 10 * Bh + bh;

    u64 Hp[20];
#pragma unroll
    for (int o2 = 0; o2 < 10; o2++) {
        float4 fu = Ub[(size_t)o2 * Bh];
        float4 fv = Vb[(size_t)o2 * Bh];
        float a0 = fmaxf(fu.x + fv.x, 0.0f);   // pos0, o=2o2
        float a1 = fmaxf(fu.z + fv.z, 0.0f);   // pos1, o=2o2
        float b0 = fmaxf(fu.y + fv.y, 0.0f);   // pos0, o=2o2+1
        float b1 = fmaxf(fu.w + fv.w, 0.0f);   // pos1, o=2o2+1
        Hp[2 * o2]     = f2mul(pk2(a0, a1), ycp[2 * o2]);
        Hp[2 * o2 + 1] = f2mul(pk2(b0, b1), ycp[2 * o2 + 1]);
    }

    float s0 = s_bfin, s1 = s_bfin;
#pragma unroll
    for (int o2 = 0; o2 < 20; o2++) {
        const ulonglong2* wr = (const ulonglong2*)(s_wd + o2 * 20);
        u64 a = s_bcd[o2];
#pragma unroll
        for (int k = 0; k < 10; k++) {
            ulonglong2 w2 = wr[k];
            a = f2fma(w2.x, Hp[2 * k],     a);
            a = f2fma(w2.y, Hp[2 * k + 1], a);
        }
        float lo, hi;
        upk2(lo, hi, a);
        float wf = s_wfin[o2];
        s0 += fmaxf(lo, 0.0f) * wf;
        s1 += fmaxf(hi, 0.0f) * wf;
    }

    ((float2*)g_S)[(size_t)pair * Bh + bh] =
        make_float2(fmaxf(s0, 0.0f), fmaxf(s1, 0.0f));
}

// ---------------------------------------------------------------------------
// Kernel 3: out[idx] = sum of g_S[7*idx .. 7*idx+6]
// ---------------------------------------------------------------------------
__global__ void frap_k3(float* __restrict__ out, int n)
{
    int idx = blockIdx.x * blockDim.x + threadIdx.x;
    if (idx >= n) return;
    const float* s = g_S + (size_t)idx * 7;
    float acc = s[0] + s[1] + s[2] + s[3] + s[4] + s[5] + s[6];
    out[idx] = acc;
}

// ---------------------------------------------------------------------------
extern "C" void kernel_launch(void* const* d_in, const int* in_sizes, int n_in,
                              void* d_out, int out_size)
{
    const float* fi        = (const float*)d_in[0];
    const float* emb_phase = (const float*)d_in[1];
    const float* w_veh     = (const float*)d_in[2];
    const float* b_veh     = (const float*)d_in[3];
    const float* w_line    = (const float*)d_in[4];
    const float* b_line    = (const float*)d_in[5];
    const float* emb_const = (const float*)d_in[6];
    const float* w_feat    = (const float*)d_in[7];
    const float* b_feat    = (const float*)d_in[8];
    const float* w_const   = (const float*)d_in[9];
    const float* b_const   = (const float*)d_in[10];
    const float* w_comb    = (const float*)d_in[11];
    const float* b_comb    = (const float*)d_in[12];
    const float* w_final   = (const float*)d_in[13];
    const float* b_final   = (const float*)d_in[14];
    const int*   cmask     = (const int*)d_in[15];

    int B = in_sizes[0] / 16;
    if (B > BMAX) B = BMAX;
    int Bh = B >> 1;

    dim3 grid1((B + 255) / 256, 8);
    dim3 grid2((Bh + 255) / 256, 56);
    int n = B * 8;
    int blocks3 = (n + 255) / 256;

    frap_k1<<<grid1, 256>>>(fi, emb_phase, w_veh, b_veh, w_line, b_line,
                            w_feat, b_feat, B);
    frap_k2<<<grid2, 256>>>(emb_const, w_const, b_const, w_comb, b_comb,
                            w_final, b_final, cmask, B);
    frap_k3<<<blocks3, 256>>>((float*)d_out, n);
}